// round 13
// baseline (speedup 1.0000x reference)
#include <cuda_runtime.h>

#define NB   16
#define NH   32
#define HD   64
#define TT   8192
#define NX   2048
#define TC   1024              // t-chunk per CTA
#define NCHUNK (TT / TC)       // 8
#define NCTA_CHUNK (NB * NH * NCHUNK)   // 4096
#define NBH  (NB * NH)                  // 512
#define THREADS 256
#define WARP_T 128             // t-slice per warp (TC / 8 warps)

// deterministic scratch: partial[bh][chunk][d]
__device__ float        g_partial[NBH * NCHUNK * HD];
__device__ unsigned int g_count[NBH];      // zero-init; reset by reducer each run

__global__ __launch_bounds__(THREADS, 4)
void attn_onepass_kernel(const float* __restrict__ q,
                         const float* __restrict__ k,
                         const float* __restrict__ v,
                         const float* __restrict__ past_k,
                         const float* __restrict__ past_v,
                         float* __restrict__ out)
{
    const int bid = blockIdx.x;
    const int tid = threadIdx.x;

    if (bid < NCTA_CHUNK) {
        // ================= streaming chunk CTA (warp-autonomous) ===========
        const int bh    = bid >> 3;        // bh-major: all 8 chunks adjacent
        const int chunk = bid & 7;
        const int warp  = tid >> 5;
        const int lane  = tid & 31;

        __shared__ float qs[HD];
        __shared__ float w[TC];            // 4 KB, warp-private 128-slices
        __shared__ float red[16 * HD];     // 4 KB

        if (tid < HD)
            qs[tid] = q[(size_t)bh * HD + tid];
        __syncthreads();                   // qs ready (only CTA barrier pre-stream)

        const int t0 = warp * WARP_T;      // this warp's t-slice within chunk

        // ---- Phase A: w[t] = sum_d q[d] * K[d, t] over warp slice ----
        // past_k: [B,H,HD,T], contiguous in t
        const float* Kp = past_k + (size_t)bh * HD * TT + (size_t)chunk * TC;
        {
            const int t = t0 + lane * 4;   // 32 lanes * 4 = 128 = WARP_T
            float4 acc = make_float4(0.f, 0.f, 0.f, 0.f);
            #pragma unroll 16
            for (int d = 0; d < HD; d++) {
                const float4 kk = __ldcs(reinterpret_cast<const float4*>(Kp + (size_t)d * TT + t));
                const float qd = qs[d];
                acc.x = fmaf(qd, kk.x, acc.x);
                acc.y = fmaf(qd, kk.y, acc.y);
                acc.z = fmaf(qd, kk.z, acc.z);
                acc.w = fmaf(qd, kk.w, acc.w);
            }
            *reinterpret_cast<float4*>(&w[t]) = acc;
        }
        __syncwarp();                      // w slice visible within warp only

        // ---- Phase B: acc[d] = sum_{t in slice} w[t] * V[t, d] ----
        // past_v: [B,H,T,HD], contiguous in d (256B rows)
        const float* Vp = past_v + (size_t)bh * TT * HD + (size_t)chunk * TC * HD;
        const int dg = lane & 15;          // d-group (float4), 0..15
        const int tg = lane >> 4;          // t parity, 0..1

        float4 acc = make_float4(0.f, 0.f, 0.f, 0.f);
        #pragma unroll 8
        for (int t = t0 + tg; t < t0 + WARP_T; t += 2) {
            const float  wt = w[t];
            const float4 vv = __ldcs(reinterpret_cast<const float4*>(Vp + (size_t)t * HD + dg * 4));
            acc.x = fmaf(wt, vv.x, acc.x);
            acc.y = fmaf(wt, vv.y, acc.y);
            acc.z = fmaf(wt, vv.z, acc.z);
            acc.w = fmaf(wt, vv.w, acc.w);
        }
        *reinterpret_cast<float4*>(&red[(warp * 2 + tg) * HD + dg * 4]) = acc;
        __syncthreads();                   // single post-stream CTA barrier

        if (tid < HD) {
            float s = 0.f;
            #pragma unroll
            for (int g = 0; g < 16; g++) s += red[g * HD + tid];
            g_partial[((size_t)bh * NCHUNK + chunk) * HD + tid] = s;
        }
        __syncthreads();                   // CTA-wide: partial stores done

        if (tid == 0) {
            __threadfence();               // release partials (single fence)
            atomicAdd(&g_count[bh], 1u);
        }
    } else {
        // ================= reducer CTA (dispatched after all chunk CTAs) ===
        const int bh = bid - NCTA_CHUNK;           // 0..511
        const size_t base = (size_t)bh * HD;

        __shared__ float prod[HD];

        // prolog, independent of partials
        float vd = 0.f;
        if (tid < HD) {
            const float qd = q[base + tid];
            const float kd = k[base + tid];
            vd = v[base + tid];
            prod[tid] = qd * kd;
        }

        if (tid == 0) {
            volatile unsigned int* cnt = &g_count[bh];
            while (*cnt < NCHUNK) __nanosleep(128);
            __threadfence();               // acquire partials
        }
        __syncthreads();                   // broadcast visibility

        if (tid < HD) {
            float wc = 0.f;
            #pragma unroll
            for (int i = 0; i < HD; i++) wc += prod[i];   // fixed order -> deterministic

            float s = 0.f;
            #pragma unroll
            for (int c = 0; c < NCHUNK; c++)
                s += __ldcg(&g_partial[base * NCHUNK + (size_t)c * HD + tid]);

            out[base + tid] = fmaf(wc, vd, s);
        }
        if (tid == 0) g_count[bh] = 0;     // reset for next graph replay
    }
}

extern "C" void kernel_launch(void* const* d_in, const int* in_sizes, int n_in,
                              void* d_out, int out_size)
{
    const float* q      = (const float*)d_in[0];
    const float* k      = (const float*)d_in[1];
    const float* v      = (const float*)d_in[2];
    const float* past_k = (const float*)d_in[3];
    const float* past_v = (const float*)d_in[4];
    float* out          = (float*)d_out;

    attn_onepass_kernel<<<NCTA_CHUNK + NBH, THREADS>>>(q, k, v, past_k, past_v, out);
}

// round 14
// speedup vs baseline: 1.0131x; 1.0131x over previous
#include <cuda_runtime.h>

#define NB   16
#define NH   32
#define HD   64
#define TT   8192
#define NX   2048
#define TC   1024              // t-chunk per CTA
#define NCHUNK (TT / TC)       // 8
#define NCTA_CHUNK (NB * NH * NCHUNK)   // 4096
#define NBH  (NB * NH)                  // 512
#define THREADS 256

// deterministic scratch: partial[bh][chunk][d]
__device__ float        g_partial[NBH * NCHUNK * HD];
__device__ unsigned int g_count[NBH];      // zero-init; reset by reducer each run

__device__ __forceinline__ float4 ldg_l2only(const float4* p) {
    // ld.global.cg: bypass L1, cache at L2 — zero-reuse streaming data
    return __ldcg(p);
}

__global__ __launch_bounds__(THREADS, 4)
void attn_onepass_kernel(const float* __restrict__ q,
                         const float* __restrict__ k,
                         const float* __restrict__ v,
                         const float* __restrict__ past_k,
                         const float* __restrict__ past_v,
                         float* __restrict__ out)
{
    const int bid = blockIdx.x;
    const int tid = threadIdx.x;

    if (bid < NCTA_CHUNK) {
        // ================= streaming chunk CTA (R8 form) ===================
        const int bh    = bid >> 3;        // bh-major: all 8 chunks adjacent
        const int chunk = bid & 7;

        __shared__ float qs[HD];
        __shared__ float w[TC];            // 4 KB
        __shared__ float red[16 * HD];     // 4 KB

        if (tid < HD)
            qs[tid] = q[(size_t)bh * HD + tid];
        __syncthreads();

        // ---- Phase A: w[t] = sum_d q[d] * K[d, t] over this chunk ----
        const float* Kp = past_k + (size_t)bh * HD * TT + (size_t)chunk * TC;
        {
            const int t = tid * 4;         // 256 * 4 = 1024 = TC
            float4 acc = make_float4(0.f, 0.f, 0.f, 0.f);
            #pragma unroll 16
            for (int d = 0; d < HD; d++) {
                const float4 kk = ldg_l2only(reinterpret_cast<const float4*>(Kp + (size_t)d * TT + t));
                const float qd = qs[d];
                acc.x = fmaf(qd, kk.x, acc.x);
                acc.y = fmaf(qd, kk.y, acc.y);
                acc.z = fmaf(qd, kk.z, acc.z);
                acc.w = fmaf(qd, kk.w, acc.w);
            }
            *reinterpret_cast<float4*>(&w[t]) = acc;
        }
        __syncthreads();

        // ---- Phase B: partial[d] = sum_{t in chunk} w[t] * V[t, d] ----
        const float* Vp = past_v + (size_t)bh * TT * HD + (size_t)chunk * TC * HD;
        const int dg = tid & 15;
        const int tg = tid >> 4;

        float4 acc = make_float4(0.f, 0.f, 0.f, 0.f);
        #pragma unroll 8
        for (int t = tg; t < TC; t += 16) {
            const float  wt = w[t];
            const float4 vv = ldg_l2only(reinterpret_cast<const float4*>(Vp + (size_t)t * HD + dg * 4));
            acc.x = fmaf(wt, vv.x, acc.x);
            acc.y = fmaf(wt, vv.y, acc.y);
            acc.z = fmaf(wt, vv.z, acc.z);
            acc.w = fmaf(wt, vv.w, acc.w);
        }
        *reinterpret_cast<float4*>(&red[tg * HD + dg * 4]) = acc;
        __syncthreads();

        if (tid < HD) {
            float s = 0.f;
            #pragma unroll
            for (int g = 0; g < 16; g++) s += red[g * HD + tid];
            g_partial[((size_t)bh * NCHUNK + chunk) * HD + tid] = s;
        }
        __syncthreads();                   // CTA-wide: partial stores done

        if (tid == 0) {
            __threadfence();               // release partials (single fence)
            atomicAdd(&g_count[bh], 1u);
        }
    } else {
        // ================= reducer CTA (dispatched after all chunk CTAs) ===
        const int bh = bid - NCTA_CHUNK;           // 0..511
        const size_t base = (size_t)bh * HD;

        __shared__ float prod[HD];

        // prolog, independent of partials
        float vd = 0.f;
        if (tid < HD) {
            const float qd = q[base + tid];
            const float kd = k[base + tid];
            vd = v[base + tid];
            prod[tid] = qd * kd;
        }

        if (tid == 0) {
            volatile unsigned int* cnt = &g_count[bh];
            while (*cnt < NCHUNK) __nanosleep(128);
            __threadfence();               // acquire partials
        }
        __syncthreads();                   // broadcast visibility

        if (tid < HD) {
            float wc = 0.f;
            #pragma unroll
            for (int i = 0; i < HD; i++) wc += prod[i];   // fixed order -> deterministic

            float s = 0.f;
            #pragma unroll
            for (int c = 0; c < NCHUNK; c++)
                s += __ldcg(&g_partial[base * NCHUNK + (size_t)c * HD + tid]);

            out[base + tid] = fmaf(wc, vd, s);
        }
        if (tid == 0) g_count[bh] = 0;     // reset for next graph replay
    }
}

extern "C" void kernel_launch(void* const* d_in, const int* in_sizes, int n_in,
                              void* d_out, int out_size)
{
    const float* q      = (const float*)d_in[0];
    const float* k      = (const float*)d_in[1];
    const float* v      = (const float*)d_in[2];
    const float* past_k = (const float*)d_in[3];
    const float* past_v = (const float*)d_in[4];
    float* out          = (float*)d_out;

    attn_onepass_kernel<<<NCTA_CHUNK + NBH, THREADS>>>(q, k, v, past_k, past_v, out);
}